// round 15
// baseline (speedup 1.0000x reference)
#include <cuda_runtime.h>
#include <math.h>

// Fixed shapes for EpisodicMemory_57810259804539
#define BB 4
#define HH 16
#define SS 2048
#define DD 64
#define MM 1000
#define KK 10
#define HID (HH*DD)       // 1024
#define TT (SS+KK)        // 2058
#define EPSV 1e-8f

#define N0_4  (BB*SS*HID/4)          // 2,097,152  inputs as float4
#define NQ_4  N0_4                    // q as float4
#define NK_4  (BB*HH*TT*DD/4)         // 2,107,392  k_aug/v_aug as float4
#define HID4  (HID/4)                 // 256 float4 per memory row

#define OUT4_TOTAL  (N0_4 + NQ_4 + 2*NK_4)          // 8,409,088
#define COPY_BLOCKS ((OUT4_TOTAL + 255) / 256)      // 32,848

// Scratch
__device__ float g_sims[BB*MM];

// ---------------------------------------------------------------------------
// K1: sims, one block per memory row m. Each thread owns one float4 of the
// row; computes ||row|| partial + dots against ALL 4 batch query keys.
// ---------------------------------------------------------------------------
__global__ void __launch_bounds__(256) k1_sims(
    const float4* __restrict__ k4,
    const float4* __restrict__ mk4)
{
    int m   = blockIdx.x;
    int tid = threadIdx.x;
    int wid = tid >> 5, lane = tid & 31;

    float4 r = mk4[m * HID4 + tid];
    float sq = r.x*r.x + r.y*r.y + r.z*r.z + r.w*r.w;

    // query_key[b][i] = k[b, i/64, S-1, i%64]; float4 chunk tid never crosses h
    int h = tid >> 4, d4 = tid & 15;
    float d[BB];
    #pragma unroll
    for (int b = 0; b < BB; b++) {
        float4 qv = k4[((b*HH + h)*SS + (SS-1))*16 + d4];
        d[b] = qv.x*r.x + qv.y*r.y + qv.z*r.z + qv.w*r.w;
    }

    #pragma unroll
    for (int off = 16; off; off >>= 1) {
        sq += __shfl_down_sync(0xffffffffu, sq, off);
        #pragma unroll
        for (int b = 0; b < BB; b++)
            d[b] += __shfl_down_sync(0xffffffffu, d[b], off);
    }

    __shared__ float red[8][5];
    if (lane == 0) {
        red[wid][0] = sq;
        #pragma unroll
        for (int b = 0; b < BB; b++) red[wid][1 + b] = d[b];
    }
    __syncthreads();

    // parallel cross-warp tail: thread t<5 sums its value across 8 warps
    __shared__ float fin[5];
    if (tid < 5) {
        float s = 0.f;
        #pragma unroll
        for (int w = 0; w < 8; w++) s += red[w][tid];
        fin[tid] = s;
    }
    __syncthreads();
    if (tid == 0) {
        float inv = 1.0f / (sqrtf(fin[0]) + EPSV);
        g_sims[0*MM + m] = fin[1] * inv;
        g_sims[1*MM + m] = fin[2] * inv;
        g_sims[2*MM + m] = fin[3] * inv;
        g_sims[3*MM + m] = fin[4] * inv;
    }
}

// ---------------------------------------------------------------------------
// K2: blocks [0, COPY_BLOCKS)      -> copy, byte-identical indexing to the
//                                     proven 40us pure-copy kernel (no -BB
//                                     shift, retrieval NOT in wave 1).
//     blocks [COPY_BLOCKS, +BB)    -> retrieval for batch b, scheduled in
//                                     the last partial wave (idle slots).
// g_sims valid via kernel boundary.
// ---------------------------------------------------------------------------
__global__ void __launch_bounds__(256) k2_main(
    const float4* __restrict__ inputs4, const float4* __restrict__ q4,
    const float4* __restrict__ k4, const float4* __restrict__ v4,
    const float4* __restrict__ mk4, const float4* __restrict__ mv4,
    const float*  __restrict__ attn_mask,
    const float*  __restrict__ mem_pos,
    float4* __restrict__ out4,
    float*  __restrict__ out,
    int off_mask, int off_pos, int off_seq, int has_scalar)
{
    const int OFFK4 = N0_4 + NQ_4;            // k_aug start (float4)
    const int OFFV4 = OFFK4 + NK_4;           // v_aug start
    int tid = threadIdx.x;

    if (blockIdx.x < COPY_BLOCKS) {
        // ---------------- copy: identical to the pure 40us kernel --------
        int e = (int)blockIdx.x * 256 + tid;
        if (e < N0_4) { out4[e] = inputs4[e]; return; }
        if (e < N0_4 + NQ_4) { out4[e] = q4[e - N0_4]; return; }
        int e2 = e - (N0_4 + NQ_4);
        if (e2 >= 2*NK_4) return;
        int which = e2 >= NK_4;
        int e3 = which ? e2 - NK_4 : e2;
        int d4 = e3 & 15;
        int r  = e3 >> 4;                     // bh*TT + t
        int t  = r % TT;
        int bh = r / TT;
        if (t < KK) return;                   // retrieval blocks own these
        const float4* s = which ? v4 : k4;
        out4[e] = s[(bh*SS + (t - KK))*16 + d4];
        return;
    }

    // ---------------- retrieval block for batch b (grid tail) ------------
    int b = (int)blockIdx.x - COPY_BLOCKS;

    __shared__ float ss[MM];
    __shared__ float rv[256];
    __shared__ int   ri[256];
    __shared__ int   top[KK];

    for (int i = tid; i < MM; i += 256)
        ss[i] = g_sims[b*MM + i];
    __syncthreads();

    // top-10: descending, lowest index on ties
    for (int j = 0; j < KK; j++) {
        float bv = -INFINITY; int bi = MM;
        for (int m = tid; m < MM; m += 256) {
            float vv = ss[m];
            if (vv > bv) { bv = vv; bi = m; }   // strict > => lowest idx wins
        }
        rv[tid] = bv; ri[tid] = bi;
        __syncthreads();
        for (int off = 128; off; off >>= 1) {
            if (tid < off) {
                float ov = rv[tid + off]; int oi = ri[tid + off];
                if (ov > rv[tid] || (ov == rv[tid] && oi < ri[tid])) {
                    rv[tid] = ov; ri[tid] = oi;
                }
            }
            __syncthreads();
        }
        if (tid == 0) { top[j] = ri[0]; ss[ri[0]] = -INFINITY; }
        __syncthreads();
    }

    // gather retrieved rows t<K of k_aug / v_aug (5120 float4)
    for (int e = tid; e < 2*KK*HID4; e += 256) {
        int which = e >= KK*HID4;
        int e2 = which ? e - KK*HID4 : e;
        int t  = e2 >> 8;
        int i4 = e2 & 255;
        int idx = top[t];
        float4 val = (which ? mv4 : mk4)[(size_t)idx*HID4 + i4];
        int dst = (which ? OFFV4 : OFFK4)
                + ((b*HH + (i4 >> 4))*TT + t)*16 + (i4 & 15);
        out4[dst] = val;
    }

    // mask_aug[b] = [ones(K), attention_mask[b]]
    for (int t = tid; t < TT; t += 256)
        out[off_mask + b*TT + t] =
            (t < KK) ? 1.0f : attn_mask[b*SS + (t - KK)];

    // positions_k[b] = [arange(S), mem_positions[top_idx[b]]]
    for (int t = tid; t < TT; t += 256)
        out[off_pos + b*TT + t] =
            (t < SS) ? (float)t : mem_pos[top[t - SS]];

    if (b == 0 && tid == 0 && has_scalar)
        out[off_seq] = (float)TT;
}

// ---------------------------------------------------------------------------
extern "C" void kernel_launch(void* const* d_in, const int* in_sizes, int n_in,
                              void* d_out, int out_size)
{
    const float* inputs = (const float*)d_in[0];
    const float* q      = (const float*)d_in[1];
    const float* k      = (const float*)d_in[2];
    const float* v      = (const float*)d_in[3];
    const float* mask   = (const float*)d_in[4];
    const float* mk     = (const float*)d_in[5];
    const float* mv     = (const float*)d_in[6];
    const float* mpos   = (const float*)d_in[7];
    float* out = (float*)d_out;

    const int off_mask = OUT4_TOTAL * 4;                 // after the 4 big tensors
    const int off_tail = off_mask + BB * TT;
    // tuple order: inputs, q, k_aug, v_aug, mask_aug, seq_len_k, positions_k
    const int with_scalar = off_tail + 1 + BB * TT;
    int has_scalar = (out_size == with_scalar) ? 1 : 0;
    const int off_seq = off_tail;
    const int off_pos = off_tail + (has_scalar ? 1 : 0);

    // K1: sims (one block per memory row)
    k1_sims<<<MM, 256>>>((const float4*)k, (const float4*)mk);

    // K2: copy (wave-1 pure) + retrieval at the grid tail — 2 nodes total
    k2_main<<<COPY_BLOCKS + BB, 256>>>(
        (const float4*)inputs, (const float4*)q,
        (const float4*)k, (const float4*)v,
        (const float4*)mk, (const float4*)mv,
        mask, mpos,
        (float4*)out, out,
        off_mask, off_pos, off_seq, has_scalar);
}

// round 16
// speedup vs baseline: 1.4372x; 1.4372x over previous
#include <cuda_runtime.h>
#include <math.h>

// Fixed shapes for EpisodicMemory_57810259804539
#define BB 4
#define HH 16
#define SS 2048
#define DD 64
#define MM 1000
#define KK 10
#define HID (HH*DD)       // 1024
#define TT (SS+KK)        // 2058
#define EPSV 1e-8f

#define N0_4  (BB*SS*HID/4)          // 2,097,152  inputs as float4
#define NQ_4  N0_4                    // q as float4
#define NK_4  (BB*HH*TT*DD/4)         // 2,107,392  k_aug/v_aug as float4
#define HID4  (HID/4)                 // 256 float4 per memory row

#define OUT4_TOTAL  (N0_4 + NQ_4 + 2*NK_4)          // 8,409,088
#define COPY_BLOCKS ((OUT4_TOTAL + 255) / 256)      // 32,848

// Scratch
__device__ float g_sims[BB*MM];

// ---------------------------------------------------------------------------
// K1: sims, one block per memory row m. Each thread owns one float4 of the
// row and computes ||row|| partial + dots against ALL 4 batch query keys
// (row loaded once instead of 4x).
// ---------------------------------------------------------------------------
__global__ void __launch_bounds__(256) k1_sims(
    const float4* __restrict__ k4,
    const float4* __restrict__ mk4)
{
    int m   = blockIdx.x;
    int tid = threadIdx.x;
    int wid = tid >> 5, lane = tid & 31;

    float4 r = mk4[m * HID4 + tid];
    float sq = r.x*r.x + r.y*r.y + r.z*r.z + r.w*r.w;

    // query_key[b][i] = k[b, i/64, S-1, i%64]; float4 chunk tid never crosses h
    int h = tid >> 4, d4 = tid & 15;
    float d[BB];
    #pragma unroll
    for (int b = 0; b < BB; b++) {
        float4 qv = k4[((b*HH + h)*SS + (SS-1))*16 + d4];
        d[b] = qv.x*r.x + qv.y*r.y + qv.z*r.z + qv.w*r.w;
    }

    // warp reduce 5 values
    #pragma unroll
    for (int off = 16; off; off >>= 1) {
        sq += __shfl_down_sync(0xffffffffu, sq, off);
        #pragma unroll
        for (int b = 0; b < BB; b++)
            d[b] += __shfl_down_sync(0xffffffffu, d[b], off);
    }

    __shared__ float red[8][5];
    if (lane == 0) {
        red[wid][0] = sq;
        #pragma unroll
        for (int b = 0; b < BB; b++) red[wid][1 + b] = d[b];
    }
    __syncthreads();

    if (tid == 0) {
        float s0 = 0.f, s1 = 0.f, s2 = 0.f, s3 = 0.f, s4 = 0.f;
        #pragma unroll
        for (int w = 0; w < 8; w++) {
            s0 += red[w][0]; s1 += red[w][1]; s2 += red[w][2];
            s3 += red[w][3]; s4 += red[w][4];
        }
        float inv = 1.0f / (sqrtf(s0) + EPSV);
        g_sims[0*MM + m] = s1 * inv;
        g_sims[1*MM + m] = s2 * inv;
        g_sims[2*MM + m] = s3 * inv;
        g_sims[3*MM + m] = s4 * inv;
    }
}

// ---------------------------------------------------------------------------
// K2: blocks 0..3  -> retrieval: top-10 (descending, lowest index on ties),
//                    gather t<K rows of k_aug/v_aug, mask_aug, positions_k,
//                    scalar. g_sims valid via kernel boundary.
//     blocks 4..   -> output-major copy, 1 float4/thread (proven shape);
//                    t<K rows skipped (retrieval owns them).
// ---------------------------------------------------------------------------
__global__ void __launch_bounds__(256) k2_main(
    const float4* __restrict__ inputs4, const float4* __restrict__ q4,
    const float4* __restrict__ k4, const float4* __restrict__ v4,
    const float4* __restrict__ mk4, const float4* __restrict__ mv4,
    const float*  __restrict__ attn_mask,
    const float*  __restrict__ mem_pos,
    float4* __restrict__ out4,
    float*  __restrict__ out,
    int off_mask, int off_pos, int off_seq, int has_scalar)
{
    const int OFFK4 = N0_4 + NQ_4;            // k_aug start (float4)
    const int OFFV4 = OFFK4 + NK_4;           // v_aug start
    int tid = threadIdx.x;

    if (blockIdx.x >= BB) {
        // ---------------- copy blocks: enumerate OUTPUT index ------------
        int e = (int)(blockIdx.x - BB) * 256 + tid;
        if (e < N0_4) { out4[e] = inputs4[e]; return; }
        if (e < N0_4 + NQ_4) { out4[e] = q4[e - N0_4]; return; }
        int e2 = e - (N0_4 + NQ_4);
        if (e2 >= 2*NK_4) return;
        int which = e2 >= NK_4;
        int e3 = which ? e2 - NK_4 : e2;
        int d4 = e3 & 15;
        int r  = e3 >> 4;                     // bh*TT + t
        int t  = r % TT;
        int bh = r / TT;
        if (t < KK) return;                   // retrieval blocks own these
        const float4* s = which ? v4 : k4;
        out4[e] = s[(bh*SS + (t - KK))*16 + d4];
        return;
    }

    // ---------------- retrieval block for batch b ------------------------
    int b = blockIdx.x;
    __shared__ float ss[MM];
    __shared__ float rv[256];
    __shared__ int   ri[256];
    __shared__ int   top[KK];

    for (int i = tid; i < MM; i += 256)
        ss[i] = g_sims[b*MM + i];
    __syncthreads();

    // top-10: descending, lowest index on ties
    for (int j = 0; j < KK; j++) {
        float bv = -INFINITY; int bi = MM;
        for (int m = tid; m < MM; m += 256) {
            float vv = ss[m];
            if (vv > bv) { bv = vv; bi = m; }   // strict > => lowest idx wins
        }
        rv[tid] = bv; ri[tid] = bi;
        __syncthreads();
        for (int off = 128; off; off >>= 1) {
            if (tid < off) {
                float ov = rv[tid + off]; int oi = ri[tid + off];
                if (ov > rv[tid] || (ov == rv[tid] && oi < ri[tid])) {
                    rv[tid] = ov; ri[tid] = oi;
                }
            }
            __syncthreads();
        }
        if (tid == 0) { top[j] = ri[0]; ss[ri[0]] = -INFINITY; }
        __syncthreads();
    }

    // gather retrieved rows t<K of k_aug / v_aug (5120 float4)
    for (int e = tid; e < 2*KK*HID4; e += 256) {
        int which = e >= KK*HID4;
        int e2 = which ? e - KK*HID4 : e;
        int t  = e2 >> 8;
        int i4 = e2 & 255;
        int idx = top[t];
        float4 val = (which ? mv4 : mk4)[(size_t)idx*HID4 + i4];
        int dst = (which ? OFFV4 : OFFK4)
                + ((b*HH + (i4 >> 4))*TT + t)*16 + (i4 & 15);
        out4[dst] = val;
    }

    // mask_aug[b] = [ones(K), attention_mask[b]]
    for (int t = tid; t < TT; t += 256)
        out[off_mask + b*TT + t] =
            (t < KK) ? 1.0f : attn_mask[b*SS + (t - KK)];

    // positions_k[b] = [arange(S), mem_positions[top_idx[b]]]
    for (int t = tid; t < TT; t += 256)
        out[off_pos + b*TT + t] =
            (t < SS) ? (float)t : mem_pos[top[t - SS]];

    if (b == 0 && tid == 0 && has_scalar)
        out[off_seq] = (float)TT;
}

// ---------------------------------------------------------------------------
extern "C" void kernel_launch(void* const* d_in, const int* in_sizes, int n_in,
                              void* d_out, int out_size)
{
    const float* inputs = (const float*)d_in[0];
    const float* q      = (const float*)d_in[1];
    const float* k      = (const float*)d_in[2];
    const float* v      = (const float*)d_in[3];
    const float* mask   = (const float*)d_in[4];
    const float* mk     = (const float*)d_in[5];
    const float* mv     = (const float*)d_in[6];
    const float* mpos   = (const float*)d_in[7];
    float* out = (float*)d_out;

    const int off_mask = OUT4_TOTAL * 4;                 // after the 4 big tensors
    const int off_tail = off_mask + BB * TT;
    // tuple order: inputs, q, k_aug, v_aug, mask_aug, seq_len_k, positions_k
    const int with_scalar = off_tail + 1 + BB * TT;
    int has_scalar = (out_size == with_scalar) ? 1 : 0;
    const int off_seq = off_tail;
    const int off_pos = off_tail + (has_scalar ? 1 : 0);

    // K1: sims, one block per memory row (row loaded once for all 4 batches)
    k1_sims<<<MM, 256>>>((const float4*)k, (const float4*)mk);

    // K2: retrieval + full copy in one kernel (proven best copy shape)
    k2_main<<<BB + COPY_BLOCKS, 256>>>(
        (const float4*)inputs, (const float4*)q,
        (const float4*)k, (const float4*)v,
        (const float4*)mk, (const float4*)mv,
        mask, mpos,
        (float4*)out, out,
        off_mask, off_pos, off_seq, has_scalar);
}